// round 16
// baseline (speedup 1.0000x reference)
#include <cuda_runtime.h>
#include <cuda_fp16.h>
#include <math.h>
#include <stdint.h>

#define NROWS 8192
#define KDIM  300
#define KPAD  320           // 10 chunks of 32
#define NCHUNK 10
#define NGRP  101
#define C1    144.26950408889634f   // 100 * log2(e)
#define LN2   0.6931471805599453f

// ---------------- static device scratch ----------------
__device__ __half g_xh [NROWS * KPAD];   // fp16, k-permuted
__device__ __half g_W1h[KPAD * KPAD];    // transposed [n][k], fp16, k-permuted
__device__ __half g_W2h[KPAD * KPAD];
__device__ float  g_b1p[KPAD];
__device__ float  g_b2p[KPAD];
__device__ __half g_h1h[NROWS * KPAD];   // fp16, k-permuted
__device__ __half g_fh [NROWS * KPAD];   // fp16, k-permuted, UNNORMALIZED h2
__device__ float  g_ss [NROWS];          // row sum-of-squares of h2
__device__ float  g_Epos[NROWS];
__device__ float  g_Eneg[NROWS];
__device__ float  g_Lpos[NROWS];         // log2 units

// ---------------- helpers ----------------
__device__ __forceinline__ int perm_col(int k) {
    return (k & ~31) + ((k & 7) >> 1) * 8 + ((k >> 4) & 1) * 4 + ((k >> 3) & 1) * 2 + (k & 1);
}
__device__ __forceinline__ int inv_perm_col(int p) {
    int q = p & 31;
    int cl = q >> 3, ks = (q >> 2) & 1, h = (q >> 1) & 1, b = q & 1;
    return (p & ~31) + ks * 16 + h * 8 + cl * 2 + b;
}

__device__ __forceinline__ uint32_t smem_u32(const void* p) {
    uint32_t a;
    asm("{ .reg .u64 t; cvta.to.shared.u64 t, %1; cvt.u32.u64 %0, t; }" : "=r"(a) : "l"(p));
    return a;
}
__device__ __forceinline__ void cp_async16(uint32_t dst, const void* src) {
    asm volatile("cp.async.cg.shared.global [%0], [%1], 16;" :: "r"(dst), "l"(src));
}
#define CP_COMMIT() asm volatile("cp.async.commit_group;" ::: "memory")
#define CP_WAIT(n)  asm volatile("cp.async.wait_group %0;" :: "n"(n) : "memory")

__device__ __forceinline__ void mma_f16(float* d, const uint32_t* a, const uint32_t* b) {
    asm volatile(
        "mma.sync.aligned.m16n8k16.row.col.f32.f16.f16.f32 "
        "{%0,%1,%2,%3}, {%4,%5,%6,%7}, {%8,%9}, {%0,%1,%2,%3};"
        : "+f"(d[0]), "+f"(d[1]), "+f"(d[2]), "+f"(d[3])
        : "r"(a[0]), "r"(a[1]), "r"(a[2]), "r"(a[3]), "r"(b[0]), "r"(b[1]));
}

__device__ __forceinline__ float fast_ex2(float x) {
    float r;
    asm("ex2.approx.ftz.f32 %0, %1;" : "=f"(r) : "f"(x));
    return r;
}

// ---------------- fused prep: W transpose tiles (blocks 0..99) + x/bias/zero (rest) ----------------
__global__ void prep_kernel(const float* __restrict__ x,
                            const float* __restrict__ W1, const float* __restrict__ b1,
                            const float* __restrict__ W2, const float* __restrict__ b2)
{
    __shared__ float s1[32][33];
    __shared__ float s2[32][33];
    const int bid = blockIdx.x;
    const int tid = threadIdx.x;

    if (bid < 100) {
        // ---- W transpose+convert tile (32x32) ----
        const int bk = (bid % 10) * 32;
        const int bn = (bid / 10) * 32;
        for (int e = tid; e < 1024; e += 256) {
            int kk = e >> 5, nn = e & 31;
            int k = bk + kk, n = bn + nn;
            bool in = (k < KDIM) && (n < KDIM);
            s1[kk][nn] = in ? W1[k * KDIM + n] : 0.0f;
            s2[kk][nn] = in ? W2[k * KDIM + n] : 0.0f;
        }
        __syncthreads();
        int t = tid & 127;
        int nl = t >> 2, vv = t & 3;
        float (*s)[33] = (tid < 128) ? s1 : s2;
        __half* dst = (tid < 128) ? g_W1h : g_W2h;
        __half h[8];
#pragma unroll
        for (int q = 0; q < 8; ++q) {
            int kl = inv_perm_col(vv * 8 + q) & 31;
            h[q] = __float2half_rn(s[kl][nl]);
        }
        *(uint4*)(dst + (size_t)(bn + nl) * KPAD + bk + vv * 8) = *(uint4*)h;
        return;
    }

    // ---- x conversion + bias + zeroing ----
    int idx = (bid - 100) * blockDim.x + tid;
    int stride = (gridDim.x - 100) * blockDim.x;
    const int VR = KPAD / 8;   // 40 vectors per row

    for (int vec = idx; vec < NROWS * VR; vec += stride) {
        int r = vec / VR, p0 = (vec - r * VR) * 8;
        __half h[8];
#pragma unroll
        for (int q = 0; q < 8; ++q) {
            int k = inv_perm_col(p0 + q);
            h[q] = (k < KDIM) ? __float2half_rn(x[r * KDIM + k]) : __ushort_as_half(0);
        }
        ((uint4*)g_xh)[vec] = *(uint4*)h;
    }
    for (int i = idx; i < KPAD; i += stride) {
        g_b1p[i] = (i < KDIM) ? b1[i] : 0.0f;
        g_b2p[i] = (i < KDIM) ? b2[i] : 0.0f;
    }
    for (int i = idx; i < NROWS; i += stride) {
        g_Epos[i] = 0.0f; g_Eneg[i] = 0.0f; g_Lpos[i] = 0.0f; g_ss[i] = 0.0f;
    }
}

// ---------------- MLP GEMM: 64x64 tiles, 128 threads, 3-stage ----------------
#define MLP_SMEM (3 * 8192)

template <int MODE>
__global__ __launch_bounds__(128) void mlp_tc_kernel()
{
    const __half* __restrict__ A    = (MODE == 0) ? g_xh  : g_h1h;
    const __half* __restrict__ Bt   = (MODE == 0) ? g_W1h : g_W2h;
    const float*  __restrict__ bias = (MODE == 0) ? g_b1p : g_b2p;
    __half* __restrict__ C          = (MODE == 0) ? g_h1h : g_fh;

    extern __shared__ char smc[];
    const uint32_t sb = smem_u32(smc);

    const int tid  = threadIdx.x;
    const int wid  = tid >> 5;
    const int lane = tid & 31;
    const int g    = lane >> 2;
    const int cl   = lane & 3;
    const int wm   = (wid & 1) * 32;
    const int wn   = (wid >> 1) * 32;
    const int i0   = blockIdx.y * 64;
    const int n0   = blockIdx.x * 64;

    float acc[2][4][4];
#pragma unroll
    for (int mt = 0; mt < 2; mt++)
#pragma unroll
        for (int nt = 0; nt < 4; nt++)
#pragma unroll
            for (int v = 0; v < 4; v++) acc[mt][nt][v] = 0.0f;

    auto issue = [&](int c, int b) {
#pragma unroll
        for (int s = 0; s < 2; ++s) {
            int i = tid + 128 * s;
            int row = i >> 2, seg = i & 3;
            cp_async16(sb + b * 8192 + row * 64 + seg * 16,
                       A + (size_t)(i0 + row) * KPAD + c * 32 + seg * 8);
        }
#pragma unroll
        for (int s = 0; s < 2; ++s) {
            int i = tid + 128 * s;
            int row = i >> 2, seg = i & 3;
            cp_async16(sb + b * 8192 + 4096 + row * 64 + seg * 16,
                       Bt + (size_t)(n0 + row) * KPAD + c * 32 + seg * 8);
        }
        CP_COMMIT();
    };

    issue(0, 0);
    issue(1, 1);
    int bc = 0, bw = 2;
    for (int c = 0; c < NCHUNK; ++c) {
        if (c + 1 < NCHUNK) CP_WAIT(1); else CP_WAIT(0);
        __syncthreads();
        if (c + 2 < NCHUNK) issue(c + 2, bw);
        bw = (bw == 2) ? 0 : bw + 1;
        const char* Ab = smc + bc * 8192;
        const char* Bb = smc + bc * 8192 + 4096;
        bc = (bc == 2) ? 0 : bc + 1;
        uint4 qa[4], bq[4];
#pragma unroll
        for (int r = 0; r < 4; ++r)
            qa[r] = *(const uint4*)(Ab + (wm + r * 8 + g) * 64 + cl * 16);
#pragma unroll
        for (int j = 0; j < 4; ++j)
            bq[j] = *(const uint4*)(Bb + (wn + j * 8 + g) * 64 + cl * 16);
        {
            uint32_t a0[4] = { qa[0].x, qa[1].x, qa[0].y, qa[1].y };
            uint32_t a1[4] = { qa[2].x, qa[3].x, qa[2].y, qa[3].y };
#pragma unroll
            for (int j = 0; j < 4; ++j) {
                uint32_t bf[2] = { bq[j].x, bq[j].y };
                mma_f16(acc[0][j], a0, bf);
                mma_f16(acc[1][j], a1, bf);
            }
        }
        {
            uint32_t a0[4] = { qa[0].z, qa[1].z, qa[0].w, qa[1].w };
            uint32_t a1[4] = { qa[2].z, qa[3].z, qa[2].w, qa[3].w };
#pragma unroll
            for (int j = 0; j < 4; ++j) {
                uint32_t bf[2] = { bq[j].z, bq[j].w };
                mma_f16(acc[0][j], a0, bf);
                mma_f16(acc[1][j], a1, bf);
            }
        }
    }

#pragma unroll
    for (int mt = 0; mt < 2; ++mt) {
#pragma unroll
        for (int h = 0; h < 2; ++h) {
            const int r = i0 + wm + mt * 16 + h * 8 + g;
            float ssum = 0.0f;
#pragma unroll
            for (int nt = 0; nt < 4; ++nt) {
                const int col = n0 + wn + nt * 8 + 2 * cl;
                float v0 = acc[mt][nt][h * 2 + 0] + bias[col];
                float v1 = acc[mt][nt][h * 2 + 1] + bias[col + 1];
                if (MODE == 0) { v0 = fmaxf(v0, 0.0f); v1 = fmaxf(v1, 0.0f); }
                const int pc = perm_col(col);
                *(__half2*)(C + (size_t)r * KPAD + pc) = __floats2half2_rn(v0, v1);
                if (MODE == 1) ssum = fmaf(v0, v0, fmaf(v1, v1, ssum));
            }
            if (MODE == 1) {
                ssum += __shfl_xor_sync(0xffffffffu, ssum, 1);
                ssum += __shfl_xor_sync(0xffffffffu, ssum, 2);
                if (cl == 0) atomicAdd(&g_ss[r], ssum);
            }
        }
    }
}

// ---------------- contrast kernel: 128 threads, warp tile 64x64, 3-stage ----------------
// stages: 3 x 16KB = 49152; labi @49152, labj @49664, invI @50176, invJ @50688, partials @51200
#define CON_SMEM_BYTES (51200 + 768 * 4)

__global__ __launch_bounds__(128) void contrast_mma_kernel(const int* __restrict__ labels)
{
    int v = 2079 - (int)blockIdx.x;
    int t = (int)((sqrtf(8.0f * v + 1.0f) - 1.0f) * 0.5f);
    while ((t + 1) * (t + 2) / 2 <= v) ++t;
    while (t * (t + 1) / 2 > v) --t;
    const int bi = 63 - t;
    const int bj = 63 - (v - t * (t + 1) / 2);
    const int i0 = bi * 128, j0 = bj * 128;
    const bool diag = (bi == bj);

    extern __shared__ char smc[];
    const uint32_t sb = smem_u32(smc);
    int*   labi_s = (int*)(smc + 49152);
    int*   labj_s = (int*)(smc + 49664);
    float* invI_s = (float*)(smc + 50176);
    float* invJ_s = (float*)(smc + 50688);
    float* rEp = (float*)(smc + 51200);
    float* rEn = rEp + 128;
    float* rLp = rEp + 256;
    float* cEp = rEp + 384;
    float* cEn = rEp + 512;
    float* cLp = rEp + 640;

    const int tid  = threadIdx.x;
    const int wid  = tid >> 5;
    const int lane = tid & 31;
    const int g    = lane >> 2;
    const int cl   = lane & 3;
    const int wm   = (wid & 1) * 64;     // 2x2 warp grid, 64x64 warp tiles
    const int wn   = (wid >> 1) * 64;

    auto issue = [&](int c, int b) {
#pragma unroll
        for (int s = 0; s < 4; ++s) {
            int i = tid + 128 * s;
            int row = i >> 2, seg = i & 3;
            uint32_t off = b * 16384 + row * 64 + seg * 16;
            cp_async16(sb + off,        g_fh + (size_t)(i0 + row) * KPAD + c * 32 + seg * 8);
            cp_async16(sb + 8192 + off, g_fh + (size_t)(j0 + row) * KPAD + c * 32 + seg * 8);
        }
        CP_COMMIT();
    };

    issue(0, 0);
    issue(1, 1);
    labi_s[tid] = labels[i0 + tid];
    invI_s[tid] = rsqrtf(g_ss[i0 + tid]);
    labj_s[tid] = labels[j0 + tid];
    invJ_s[tid] = rsqrtf(g_ss[j0 + tid]);
    for (int q = tid; q < 768; q += 128) rEp[q] = 0.0f;

    float acc[4][8][4];
#pragma unroll
    for (int mt = 0; mt < 4; mt++)
#pragma unroll
        for (int nt = 0; nt < 8; nt++)
#pragma unroll
            for (int u = 0; u < 4; u++) acc[mt][nt][u] = 0.0f;

    int bc = 0, bw = 2;
    for (int c = 0; c < NCHUNK; ++c) {
        if (c + 1 < NCHUNK) CP_WAIT(1); else CP_WAIT(0);
        __syncthreads();
        if (c + 2 < NCHUNK) issue(c + 2, bw);
        bw = (bw == 2) ? 0 : bw + 1;
        const char* Ab = smc + bc * 16384;
        const char* Bb = smc + bc * 16384 + 8192;
        bc = (bc == 2) ? 0 : bc + 1;
        uint4 qa[8];
#pragma unroll
        for (int r = 0; r < 8; ++r)
            qa[r] = *(const uint4*)(Ab + (wm + r * 8 + g) * 64 + cl * 16);
#pragma unroll
        for (int nt = 0; nt < 8; ++nt) {
            uint4 bv = *(const uint4*)(Bb + (wn + nt * 8 + g) * 64 + cl * 16);
            uint32_t b0[2] = { bv.x, bv.y };
            uint32_t b1[2] = { bv.z, bv.w };
#pragma unroll
            for (int mt = 0; mt < 4; ++mt) {
                uint32_t alo[4] = { qa[2*mt].x, qa[2*mt+1].x, qa[2*mt].y, qa[2*mt+1].y };
                mma_f16(acc[mt][nt], alo, b0);
            }
#pragma unroll
            for (int mt = 0; mt < 4; ++mt) {
                uint32_t ahi[4] = { qa[2*mt].z, qa[2*mt+1].z, qa[2*mt].w, qa[2*mt+1].w };
                mma_f16(acc[mt][nt], ahi, b1);
            }
        }
    }

    // ---- fused epilogue with normalization: s = acc * invI[r] * invJ[col] ----
    float invR[8];
#pragma unroll
    for (int u = 0; u < 8; ++u)
        invR[u] = invI_s[wm + (u >> 1) * 16 + (u & 1) * 8 + g];

    float rp[8][3];
#pragma unroll
    for (int u = 0; u < 8; u++) { rp[u][0] = 0.f; rp[u][1] = 0.f; rp[u][2] = 0.f; }

    if (!diag) {
        // ---- off-diagonal: no self test; row + column accumulation ----
#pragma unroll
        for (int nt = 0; nt < 8; ++nt) {
            float cs[2][3] = { {0.f,0.f,0.f}, {0.f,0.f,0.f} };
#pragma unroll
            for (int q = 0; q < 2; ++q) {
                const int col = wn + nt * 8 + 2 * cl + q;
                const float ivc = invJ_s[col] * C1;
                const int lj = labj_s[col];
#pragma unroll
                for (int mt = 0; mt < 4; ++mt)
#pragma unroll
                    for (int h = 0; h < 2; ++h) {
                        const int r = wm + mt * 16 + h * 8 + g;
                        float t2 = fmaf(acc[mt][nt][h * 2 + q] * invR[mt * 2 + h], ivc, -C1);
                        float e  = fast_ex2(t2);
                        if (labi_s[r] == lj) {
                            rp[mt * 2 + h][0] += e; rp[mt * 2 + h][2] += t2;
                            cs[q][0] += e;          cs[q][2] += t2;
                        } else {
                            rp[mt * 2 + h][1] += e; cs[q][1] += e;
                        }
                    }
            }
#pragma unroll
            for (int q = 0; q < 2; ++q)
#pragma unroll
                for (int u = 0; u < 3; ++u) {
                    float xx = cs[q][u];
                    xx += __shfl_xor_sync(0xffffffffu, xx, 4);
                    xx += __shfl_xor_sync(0xffffffffu, xx, 8);
                    xx += __shfl_xor_sync(0xffffffffu, xx, 16);
                    cs[q][u] = xx;
                }
            if (g == 0) {
                const int col = wn + nt * 8 + 2 * cl;
                atomicAdd(&cEp[col],     cs[0][0]);
                atomicAdd(&cEn[col],     cs[0][1]);
                atomicAdd(&cLp[col],     cs[0][2]);
                atomicAdd(&cEp[col + 1], cs[1][0]);
                atomicAdd(&cEn[col + 1], cs[1][1]);
                atomicAdd(&cLp[col + 1], cs[1][2]);
            }
        }
    } else {
        // ---- diagonal tile: self test, rows only ----
#pragma unroll
        for (int nt = 0; nt < 8; ++nt) {
#pragma unroll
            for (int q = 0; q < 2; ++q) {
                const int col = wn + nt * 8 + 2 * cl + q;
                const float ivc = invJ_s[col] * C1;
                const int lj = labj_s[col];
#pragma unroll
                for (int mt = 0; mt < 4; ++mt)
#pragma unroll
                    for (int h = 0; h < 2; ++h) {
                        const int r = wm + mt * 16 + h * 8 + g;
                        float t2 = fmaf(acc[mt][nt][h * 2 + q] * invR[mt * 2 + h], ivc, -C1);
                        float e  = fast_ex2(t2);
                        if (r != col) {
                            if (labi_s[r] == lj) { rp[mt * 2 + h][0] += e; rp[mt * 2 + h][2] += t2; }
                            else                 { rp[mt * 2 + h][1] += e; }
                        }
                    }
            }
        }
    }

#pragma unroll
    for (int u = 0; u < 8; ++u) {
#pragma unroll
        for (int w = 0; w < 3; ++w) {
            float xx = rp[u][w];
            xx += __shfl_xor_sync(0xffffffffu, xx, 1);
            xx += __shfl_xor_sync(0xffffffffu, xx, 2);
            rp[u][w] = xx;
        }
        if (cl == 0) {
            const int r = wm + (u >> 1) * 16 + (u & 1) * 8 + g;
            atomicAdd(&rEp[r], rp[u][0]);
            atomicAdd(&rEn[r], rp[u][1]);
            atomicAdd(&rLp[r], rp[u][2]);
        }
    }
    __syncthreads();
    {
        atomicAdd(&g_Epos[i0 + tid], rEp[tid]);
        atomicAdd(&g_Eneg[i0 + tid], rEn[tid]);
        atomicAdd(&g_Lpos[i0 + tid], rLp[tid]);
        if (!diag) {
            atomicAdd(&g_Epos[j0 + tid], cEp[tid]);
            atomicAdd(&g_Eneg[j0 + tid], cEn[tid]);
            atomicAdd(&g_Lpos[j0 + tid], cLp[tid]);
        }
    }
}

// ---------------- final loss reduction (fused label histogram; Lp in log2 units) ----------------
__global__ void loss_kernel(const int* __restrict__ labels, float* __restrict__ out)
{
    __shared__ int   shist[NGRP];
    __shared__ float ssum[32], scnt[32];
    int tid = threadIdx.x;

    for (int i = tid; i < NGRP; i += blockDim.x) shist[i] = 0;
    __syncthreads();
    for (int i = tid; i < NROWS; i += blockDim.x) atomicAdd(&shist[labels[i]], 1);
    __syncthreads();

    float local = 0.0f, cnt = 0.0f;
    for (int i = tid; i < NROWS; i += blockDim.x) {
        int pc = shist[labels[i]] - 1;
        if (pc > 0) {
            int nc = NROWS - 1 - pc;
            float fpc = (float)pc;
            float Ep = g_Epos[i], En = g_Eneg[i], Lp = g_Lpos[i] * LN2;
            float denom = Ep / fpc + ((nc > 0) ? En / (float)nc : En);
            float mean  = Lp / fpc - logf(fpc) - logf(denom);
            local += mean;
            cnt += 1.0f;
        }
    }
#pragma unroll
    for (int off = 16; off > 0; off >>= 1) {
        local += __shfl_down_sync(0xffffffffu, local, off);
        cnt   += __shfl_down_sync(0xffffffffu, cnt, off);
    }
    if ((tid & 31) == 0) { ssum[tid >> 5] = local; scnt[tid >> 5] = cnt; }
    __syncthreads();
    if (tid < 32) {
        int nw = blockDim.x >> 5;
        float a = (tid < nw) ? ssum[tid] : 0.0f;
        float b = (tid < nw) ? scnt[tid] : 0.0f;
#pragma unroll
        for (int off = 16; off > 0; off >>= 1) {
            a += __shfl_down_sync(0xffffffffu, a, off);
            b += __shfl_down_sync(0xffffffffu, b, off);
        }
        if (tid == 0) out[0] = -0.01f * (a / b);
    }
}

// ---------------- launch ----------------
extern "C" void kernel_launch(void* const* d_in, const int* in_sizes, int n_in,
                              void* d_out, int out_size)
{
    const float* x      = (const float*)d_in[0];
    const float* W1     = (const float*)d_in[1];
    const float* b1     = (const float*)d_in[2];
    const float* W2     = (const float*)d_in[3];
    const float* b2     = (const float*)d_in[4];
    const int*   labels = (const int*)d_in[5];
    float* out = (float*)d_out;

    static int smem_set = 0;
    if (!smem_set) {
        cudaFuncSetAttribute(contrast_mma_kernel,
                             cudaFuncAttributeMaxDynamicSharedMemorySize, CON_SMEM_BYTES);
        cudaFuncSetAttribute(mlp_tc_kernel<0>,
                             cudaFuncAttributeMaxDynamicSharedMemorySize, MLP_SMEM);
        cudaFuncSetAttribute(mlp_tc_kernel<1>,
                             cudaFuncAttributeMaxDynamicSharedMemorySize, MLP_SMEM);
        smem_set = 1;
    }

    prep_kernel<<<1124, 256>>>(x, W1, b1, W2, b2);   // blocks 0..99 = W tiles, 100..1123 = x/bias/zero

    dim3 gm(KPAD / 64, NROWS / 64);                  // (5, 128) = 640 CTAs
    mlp_tc_kernel<0><<<gm, 128, MLP_SMEM>>>();
    mlp_tc_kernel<1><<<gm, 128, MLP_SMEM>>>();

    contrast_mma_kernel<<<2080, 128, CON_SMEM_BYTES>>>(labels);

    loss_kernel<<<1, 1024>>>(labels, out);
}

// round 17
// speedup vs baseline: 1.5639x; 1.5639x over previous
#include <cuda_runtime.h>
#include <cuda_fp16.h>
#include <math.h>
#include <stdint.h>

#define NROWS 8192
#define KDIM  300
#define KPAD  320           // 10 chunks of 32
#define NCHUNK 10
#define NGRP  101
#define C1    144.26950408889634f   // 100 * log2(e)
#define LN2   0.6931471805599453f

// ---------------- static device scratch ----------------
__device__ __half g_xh [NROWS * KPAD];   // fp16, k-permuted
__device__ __half g_W1h[KPAD * KPAD];    // transposed [n][k], fp16, k-permuted
__device__ __half g_W2h[KPAD * KPAD];
__device__ float  g_b1p[KPAD];
__device__ float  g_b2p[KPAD];
__device__ __half g_h1h[NROWS * KPAD];   // fp16, k-permuted
__device__ __half g_fh [NROWS * KPAD];   // fp16, k-permuted, UNNORMALIZED h2
__device__ float  g_ss [NROWS];          // row sum-of-squares of h2
__device__ float  g_Epos[NROWS];
__device__ float  g_Eneg[NROWS];
__device__ float  g_Lpos[NROWS];         // log2 units

// ---------------- helpers ----------------
__device__ __forceinline__ int perm_col(int k) {
    return (k & ~31) + ((k & 7) >> 1) * 8 + ((k >> 4) & 1) * 4 + ((k >> 3) & 1) * 2 + (k & 1);
}
__device__ __forceinline__ int inv_perm_col(int p) {
    int q = p & 31;
    int cl = q >> 3, ks = (q >> 2) & 1, h = (q >> 1) & 1, b = q & 1;
    return (p & ~31) + ks * 16 + h * 8 + cl * 2 + b;
}

__device__ __forceinline__ uint32_t smem_u32(const void* p) {
    uint32_t a;
    asm("{ .reg .u64 t; cvta.to.shared.u64 t, %1; cvt.u32.u64 %0, t; }" : "=r"(a) : "l"(p));
    return a;
}
__device__ __forceinline__ void cp_async16(uint32_t dst, const void* src) {
    asm volatile("cp.async.cg.shared.global [%0], [%1], 16;" :: "r"(dst), "l"(src));
}
#define CP_COMMIT() asm volatile("cp.async.commit_group;" ::: "memory")
#define CP_WAIT(n)  asm volatile("cp.async.wait_group %0;" :: "n"(n) : "memory")

__device__ __forceinline__ void mma_f16(float* d, const uint32_t* a, const uint32_t* b) {
    asm volatile(
        "mma.sync.aligned.m16n8k16.row.col.f32.f16.f16.f32 "
        "{%0,%1,%2,%3}, {%4,%5,%6,%7}, {%8,%9}, {%0,%1,%2,%3};"
        : "+f"(d[0]), "+f"(d[1]), "+f"(d[2]), "+f"(d[3])
        : "r"(a[0]), "r"(a[1]), "r"(a[2]), "r"(a[3]), "r"(b[0]), "r"(b[1]));
}

__device__ __forceinline__ float fast_ex2(float x) {
    float r;
    asm("ex2.approx.ftz.f32 %0, %1;" : "=f"(r) : "f"(x));
    return r;
}

// ---------------- fused prep: W transpose tiles (blocks 0..99) + x/bias/zero (rest) ----------------
__global__ void prep_kernel(const float* __restrict__ x,
                            const float* __restrict__ W1, const float* __restrict__ b1,
                            const float* __restrict__ W2, const float* __restrict__ b2)
{
    __shared__ float s1[32][33];
    __shared__ float s2[32][33];
    const int bid = blockIdx.x;
    const int tid = threadIdx.x;

    if (bid < 100) {
        // ---- W transpose+convert tile (32x32) ----
        const int bk = (bid % 10) * 32;
        const int bn = (bid / 10) * 32;
        for (int e = tid; e < 1024; e += 256) {
            int kk = e >> 5, nn = e & 31;
            int k = bk + kk, n = bn + nn;
            bool in = (k < KDIM) && (n < KDIM);
            s1[kk][nn] = in ? W1[k * KDIM + n] : 0.0f;
            s2[kk][nn] = in ? W2[k * KDIM + n] : 0.0f;
        }
        __syncthreads();
        int t = tid & 127;
        int nl = t >> 2, vv = t & 3;
        float (*s)[33] = (tid < 128) ? s1 : s2;
        __half* dst = (tid < 128) ? g_W1h : g_W2h;
        __half h[8];
#pragma unroll
        for (int q = 0; q < 8; ++q) {
            int kl = inv_perm_col(vv * 8 + q) & 31;
            h[q] = __float2half_rn(s[kl][nl]);
        }
        *(uint4*)(dst + (size_t)(bn + nl) * KPAD + bk + vv * 8) = *(uint4*)h;
        return;
    }

    // ---- x conversion + bias + zeroing ----
    int idx = (bid - 100) * blockDim.x + tid;
    int stride = (gridDim.x - 100) * blockDim.x;
    const int VR = KPAD / 8;   // 40 vectors per row

    for (int vec = idx; vec < NROWS * VR; vec += stride) {
        int r = vec / VR, p0 = (vec - r * VR) * 8;
        __half h[8];
#pragma unroll
        for (int q = 0; q < 8; ++q) {
            int k = inv_perm_col(p0 + q);
            h[q] = (k < KDIM) ? __float2half_rn(x[r * KDIM + k]) : __ushort_as_half(0);
        }
        ((uint4*)g_xh)[vec] = *(uint4*)h;
    }
    for (int i = idx; i < KPAD; i += stride) {
        g_b1p[i] = (i < KDIM) ? b1[i] : 0.0f;
        g_b2p[i] = (i < KDIM) ? b2[i] : 0.0f;
    }
    for (int i = idx; i < NROWS; i += stride) {
        g_Epos[i] = 0.0f; g_Eneg[i] = 0.0f; g_Lpos[i] = 0.0f; g_ss[i] = 0.0f;
    }
}

// ---------------- MLP GEMM: 64x64 tiles, 128 threads, 3-stage ----------------
#define MLP_SMEM (3 * 8192)

template <int MODE>
__global__ __launch_bounds__(128) void mlp_tc_kernel()
{
    const __half* __restrict__ A    = (MODE == 0) ? g_xh  : g_h1h;
    const __half* __restrict__ Bt   = (MODE == 0) ? g_W1h : g_W2h;
    const float*  __restrict__ bias = (MODE == 0) ? g_b1p : g_b2p;
    __half* __restrict__ C          = (MODE == 0) ? g_h1h : g_fh;

    extern __shared__ char smc[];
    const uint32_t sb = smem_u32(smc);

    const int tid  = threadIdx.x;
    const int wid  = tid >> 5;
    const int lane = tid & 31;
    const int g    = lane >> 2;
    const int cl   = lane & 3;
    const int wm   = (wid & 1) * 32;
    const int wn   = (wid >> 1) * 32;
    const int i0   = blockIdx.y * 64;
    const int n0   = blockIdx.x * 64;

    float acc[2][4][4];
#pragma unroll
    for (int mt = 0; mt < 2; mt++)
#pragma unroll
        for (int nt = 0; nt < 4; nt++)
#pragma unroll
            for (int v = 0; v < 4; v++) acc[mt][nt][v] = 0.0f;

    auto issue = [&](int c, int b) {
#pragma unroll
        for (int s = 0; s < 2; ++s) {
            int i = tid + 128 * s;
            int row = i >> 2, seg = i & 3;
            cp_async16(sb + b * 8192 + row * 64 + seg * 16,
                       A + (size_t)(i0 + row) * KPAD + c * 32 + seg * 8);
        }
#pragma unroll
        for (int s = 0; s < 2; ++s) {
            int i = tid + 128 * s;
            int row = i >> 2, seg = i & 3;
            cp_async16(sb + b * 8192 + 4096 + row * 64 + seg * 16,
                       Bt + (size_t)(n0 + row) * KPAD + c * 32 + seg * 8);
        }
        CP_COMMIT();
    };

    issue(0, 0);
    issue(1, 1);
    int bc = 0, bw = 2;
    for (int c = 0; c < NCHUNK; ++c) {
        if (c + 1 < NCHUNK) CP_WAIT(1); else CP_WAIT(0);
        __syncthreads();
        if (c + 2 < NCHUNK) issue(c + 2, bw);
        bw = (bw == 2) ? 0 : bw + 1;
        const char* Ab = smc + bc * 8192;
        const char* Bb = smc + bc * 8192 + 4096;
        bc = (bc == 2) ? 0 : bc + 1;
        uint4 qa[4], bq[4];
#pragma unroll
        for (int r = 0; r < 4; ++r)
            qa[r] = *(const uint4*)(Ab + (wm + r * 8 + g) * 64 + cl * 16);
#pragma unroll
        for (int j = 0; j < 4; ++j)
            bq[j] = *(const uint4*)(Bb + (wn + j * 8 + g) * 64 + cl * 16);
        {
            uint32_t a0[4] = { qa[0].x, qa[1].x, qa[0].y, qa[1].y };
            uint32_t a1[4] = { qa[2].x, qa[3].x, qa[2].y, qa[3].y };
#pragma unroll
            for (int j = 0; j < 4; ++j) {
                uint32_t bf[2] = { bq[j].x, bq[j].y };
                mma_f16(acc[0][j], a0, bf);
                mma_f16(acc[1][j], a1, bf);
            }
        }
        {
            uint32_t a0[4] = { qa[0].z, qa[1].z, qa[0].w, qa[1].w };
            uint32_t a1[4] = { qa[2].z, qa[3].z, qa[2].w, qa[3].w };
#pragma unroll
            for (int j = 0; j < 4; ++j) {
                uint32_t bf[2] = { bq[j].z, bq[j].w };
                mma_f16(acc[0][j], a0, bf);
                mma_f16(acc[1][j], a1, bf);
            }
        }
    }

#pragma unroll
    for (int mt = 0; mt < 2; ++mt) {
#pragma unroll
        for (int h = 0; h < 2; ++h) {
            const int r = i0 + wm + mt * 16 + h * 8 + g;
            float ssum = 0.0f;
#pragma unroll
            for (int nt = 0; nt < 4; ++nt) {
                const int col = n0 + wn + nt * 8 + 2 * cl;
                float v0 = acc[mt][nt][h * 2 + 0] + bias[col];
                float v1 = acc[mt][nt][h * 2 + 1] + bias[col + 1];
                if (MODE == 0) { v0 = fmaxf(v0, 0.0f); v1 = fmaxf(v1, 0.0f); }
                const int pc = perm_col(col);
                *(__half2*)(C + (size_t)r * KPAD + pc) = __floats2half2_rn(v0, v1);
                if (MODE == 1) ssum = fmaf(v0, v0, fmaf(v1, v1, ssum));
            }
            if (MODE == 1) {
                ssum += __shfl_xor_sync(0xffffffffu, ssum, 1);
                ssum += __shfl_xor_sync(0xffffffffu, ssum, 2);
                if (cl == 0) atomicAdd(&g_ss[r], ssum);
            }
        }
    }
}

// ---------------- contrast kernel: 128 threads, warp tile 64x64, 3-stage (R15 epilogue) ----------------
// stages: 3 x 16KB = 49152; labi @49152, labj @49664, invI @50176, invJ @50688, partials @51200
#define CON_SMEM_BYTES (51200 + 768 * 4)

__global__ __launch_bounds__(128) void contrast_mma_kernel(const int* __restrict__ labels)
{
    int v = 2079 - (int)blockIdx.x;
    int t = (int)((sqrtf(8.0f * v + 1.0f) - 1.0f) * 0.5f);
    while ((t + 1) * (t + 2) / 2 <= v) ++t;
    while (t * (t + 1) / 2 > v) --t;
    const int bi = 63 - t;
    const int bj = 63 - (v - t * (t + 1) / 2);
    const int i0 = bi * 128, j0 = bj * 128;
    const bool diag = (bi == bj);

    extern __shared__ char smc[];
    const uint32_t sb = smem_u32(smc);
    int*   labi_s = (int*)(smc + 49152);
    int*   labj_s = (int*)(smc + 49664);
    float* invI_s = (float*)(smc + 50176);
    float* invJ_s = (float*)(smc + 50688);
    float* rEp = (float*)(smc + 51200);
    float* rEn = rEp + 128;
    float* rLp = rEp + 256;
    float* cEp = rEp + 384;
    float* cEn = rEp + 512;
    float* cLp = rEp + 640;

    const int tid  = threadIdx.x;
    const int wid  = tid >> 5;
    const int lane = tid & 31;
    const int g    = lane >> 2;
    const int cl   = lane & 3;
    const int wm   = (wid & 1) * 64;     // 2x2 warp grid, 64x64 warp tiles
    const int wn   = (wid >> 1) * 64;

    auto issue = [&](int c, int b) {
#pragma unroll
        for (int s = 0; s < 4; ++s) {
            int i = tid + 128 * s;
            int row = i >> 2, seg = i & 3;
            uint32_t off = b * 16384 + row * 64 + seg * 16;
            cp_async16(sb + off,        g_fh + (size_t)(i0 + row) * KPAD + c * 32 + seg * 8);
            cp_async16(sb + 8192 + off, g_fh + (size_t)(j0 + row) * KPAD + c * 32 + seg * 8);
        }
        CP_COMMIT();
    };

    issue(0, 0);
    issue(1, 1);
    labi_s[tid] = labels[i0 + tid];
    invI_s[tid] = rsqrtf(g_ss[i0 + tid]);
    labj_s[tid] = labels[j0 + tid];
    invJ_s[tid] = rsqrtf(g_ss[j0 + tid]);
    for (int q = tid; q < 768; q += 128) rEp[q] = 0.0f;

    float acc[4][8][4];
#pragma unroll
    for (int mt = 0; mt < 4; mt++)
#pragma unroll
        for (int nt = 0; nt < 8; nt++)
#pragma unroll
            for (int u = 0; u < 4; u++) acc[mt][nt][u] = 0.0f;

    int bc = 0, bw = 2;
    for (int c = 0; c < NCHUNK; ++c) {
        if (c + 1 < NCHUNK) CP_WAIT(1); else CP_WAIT(0);
        __syncthreads();
        if (c + 2 < NCHUNK) issue(c + 2, bw);
        bw = (bw == 2) ? 0 : bw + 1;
        const char* Ab = smc + bc * 16384;
        const char* Bb = smc + bc * 16384 + 8192;
        bc = (bc == 2) ? 0 : bc + 1;
        uint4 qa[8];
#pragma unroll
        for (int r = 0; r < 8; ++r)
            qa[r] = *(const uint4*)(Ab + (wm + r * 8 + g) * 64 + cl * 16);
#pragma unroll
        for (int nt = 0; nt < 8; ++nt) {
            uint4 bv = *(const uint4*)(Bb + (wn + nt * 8 + g) * 64 + cl * 16);
            uint32_t b0[2] = { bv.x, bv.y };
            uint32_t b1[2] = { bv.z, bv.w };
#pragma unroll
            for (int mt = 0; mt < 4; ++mt) {
                uint32_t alo[4] = { qa[2*mt].x, qa[2*mt+1].x, qa[2*mt].y, qa[2*mt+1].y };
                mma_f16(acc[mt][nt], alo, b0);
            }
#pragma unroll
            for (int mt = 0; mt < 4; ++mt) {
                uint32_t ahi[4] = { qa[2*mt].z, qa[2*mt+1].z, qa[2*mt].w, qa[2*mt+1].w };
                mma_f16(acc[mt][nt], ahi, b1);
            }
        }
    }

    // ---- fused epilogue with normalization: s = acc * invI[r] * invJ[col] (unified R15 form) ----
    float invR[8];
#pragma unroll
    for (int u = 0; u < 8; ++u)
        invR[u] = invI_s[wm + (u >> 1) * 16 + (u & 1) * 8 + g];

    float rp[8][3];
#pragma unroll
    for (int u = 0; u < 8; u++) { rp[u][0] = 0.f; rp[u][1] = 0.f; rp[u][2] = 0.f; }

#pragma unroll
    for (int nt = 0; nt < 8; ++nt) {
        float cs[2][3] = { {0.f,0.f,0.f}, {0.f,0.f,0.f} };
#pragma unroll
        for (int q = 0; q < 2; ++q) {
            const int col = wn + nt * 8 + 2 * cl + q;
            const float ivc = invJ_s[col] * C1;
            const int lj = labj_s[col];
#pragma unroll
            for (int mt = 0; mt < 4; ++mt)
#pragma unroll
                for (int h = 0; h < 2; ++h) {
                    const int r = wm + mt * 16 + h * 8 + g;
                    float t2 = fmaf(acc[mt][nt][h * 2 + q] * invR[mt * 2 + h], ivc, -C1);
                    float e  = fast_ex2(t2);
                    bool self  = diag && (r == col);
                    bool match = (labi_s[r] == lj);
                    if (!self) {
                        if (match) { rp[mt * 2 + h][0] += e; rp[mt * 2 + h][2] += t2;
                                     cs[q][0] += e;          cs[q][2] += t2; }
                        else       { rp[mt * 2 + h][1] += e; cs[q][1] += e; }
                    }
                }
        }
        if (!diag) {
#pragma unroll
            for (int q = 0; q < 2; ++q)
#pragma unroll
                for (int u = 0; u < 3; ++u) {
                    float xx = cs[q][u];
                    xx += __shfl_xor_sync(0xffffffffu, xx, 4);
                    xx += __shfl_xor_sync(0xffffffffu, xx, 8);
                    xx += __shfl_xor_sync(0xffffffffu, xx, 16);
                    cs[q][u] = xx;
                }
            if (g == 0) {
                const int col = wn + nt * 8 + 2 * cl;
                atomicAdd(&cEp[col],     cs[0][0]);
                atomicAdd(&cEn[col],     cs[0][1]);
                atomicAdd(&cLp[col],     cs[0][2]);
                atomicAdd(&cEp[col + 1], cs[1][0]);
                atomicAdd(&cEn[col + 1], cs[1][1]);
                atomicAdd(&cLp[col + 1], cs[1][2]);
            }
        }
    }
#pragma unroll
    for (int u = 0; u < 8; ++u) {
#pragma unroll
        for (int w = 0; w < 3; ++w) {
            float xx = rp[u][w];
            xx += __shfl_xor_sync(0xffffffffu, xx, 1);
            xx += __shfl_xor_sync(0xffffffffu, xx, 2);
            rp[u][w] = xx;
        }
        if (cl == 0) {
            const int r = wm + (u >> 1) * 16 + (u & 1) * 8 + g;
            atomicAdd(&rEp[r], rp[u][0]);
            atomicAdd(&rEn[r], rp[u][1]);
            atomicAdd(&rLp[r], rp[u][2]);
        }
    }
    __syncthreads();
    {
        atomicAdd(&g_Epos[i0 + tid], rEp[tid]);
        atomicAdd(&g_Eneg[i0 + tid], rEn[tid]);
        atomicAdd(&g_Lpos[i0 + tid], rLp[tid]);
        if (!diag) {
            atomicAdd(&g_Epos[j0 + tid], cEp[tid]);
            atomicAdd(&g_Eneg[j0 + tid], cEn[tid]);
            atomicAdd(&g_Lpos[j0 + tid], cLp[tid]);
        }
    }
}

// ---------------- final loss reduction (fused label histogram; Lp in log2 units) ----------------
__global__ void loss_kernel(const int* __restrict__ labels, float* __restrict__ out)
{
    __shared__ int   shist[NGRP];
    __shared__ float ssum[32], scnt[32];
    int tid = threadIdx.x;

    for (int i = tid; i < NGRP; i += blockDim.x) shist[i] = 0;
    __syncthreads();
    for (int i = tid; i < NROWS; i += blockDim.x) atomicAdd(&shist[labels[i]], 1);
    __syncthreads();

    float local = 0.0f, cnt = 0.0f;
    for (int i = tid; i < NROWS; i += blockDim.x) {
        int pc = shist[labels[i]] - 1;
        if (pc > 0) {
            int nc = NROWS - 1 - pc;
            float fpc = (float)pc;
            float Ep = g_Epos[i], En = g_Eneg[i], Lp = g_Lpos[i] * LN2;
            float denom = Ep / fpc + ((nc > 0) ? En / (float)nc : En);
            float mean  = Lp / fpc - logf(fpc) - logf(denom);
            local += mean;
            cnt += 1.0f;
        }
    }
#pragma unroll
    for (int off = 16; off > 0; off >>= 1) {
        local += __shfl_down_sync(0xffffffffu, local, off);
        cnt   += __shfl_down_sync(0xffffffffu, cnt, off);
    }
    if ((tid & 31) == 0) { ssum[tid >> 5] = local; scnt[tid >> 5] = cnt; }
    __syncthreads();
    if (tid < 32) {
        int nw = blockDim.x >> 5;
        float a = (tid < nw) ? ssum[tid] : 0.0f;
        float b = (tid < nw) ? scnt[tid] : 0.0f;
#pragma unroll
        for (int off = 16; off > 0; off >>= 1) {
            a += __shfl_down_sync(0xffffffffu, a, off);
            b += __shfl_down_sync(0xffffffffu, b, off);
        }
        if (tid == 0) out[0] = -0.01f * (a / b);
    }
}

// ---------------- launch ----------------
extern "C" void kernel_launch(void* const* d_in, const int* in_sizes, int n_in,
                              void* d_out, int out_size)
{
    const float* x      = (const float*)d_in[0];
    const float* W1     = (const float*)d_in[1];
    const float* b1     = (const float*)d_in[2];
    const float* W2     = (const float*)d_in[3];
    const float* b2     = (const float*)d_in[4];
    const int*   labels = (const int*)d_in[5];
    float* out = (float*)d_out;

    static int smem_set = 0;
    if (!smem_set) {
        cudaFuncSetAttribute(contrast_mma_kernel,
                             cudaFuncAttributeMaxDynamicSharedMemorySize, CON_SMEM_BYTES);
        cudaFuncSetAttribute(mlp_tc_kernel<0>,
                             cudaFuncAttributeMaxDynamicSharedMemorySize, MLP_SMEM);
        cudaFuncSetAttribute(mlp_tc_kernel<1>,
                             cudaFuncAttributeMaxDynamicSharedMemorySize, MLP_SMEM);
        smem_set = 1;
    }

    prep_kernel<<<1124, 256>>>(x, W1, b1, W2, b2);   // blocks 0..99 = W tiles, 100..1123 = x/bias/zero

    dim3 gm(KPAD / 64, NROWS / 64);                  // (5, 128) = 640 CTAs
    mlp_tc_kernel<0><<<gm, 128, MLP_SMEM>>>();
    mlp_tc_kernel<1><<<gm, 128, MLP_SMEM>>>();

    contrast_mma_kernel<<<2080, 128, CON_SMEM_BYTES>>>(labels);

    loss_kernel<<<1, 1024>>>(labels, out);
}